// round 1
// baseline (speedup 1.0000x reference)
#include <cuda_runtime.h>
#include <math.h>

#define NB    2
#define NCAM  6
#define DIM   256
#define HWQ   2500
#define PK    625
#define NHEAD 8
#define DH    32
#define ND    1536     // NCAM*DIM
#define NKEY  3750     // NCAM*PK

// ---------------- scratch (device globals; no allocs allowed) ----------------
__device__ float g_qT    [(long)NB*HWQ*ND];          // (b, p, cam*256+c)
__device__ float g_kpool [(long)NB*PK*ND];           // (b, kk, cam*256+c)
__device__ float g_vpool [(long)NB*PK*ND];
__device__ float g_qf    [(long)NB*NCAM*HWQ*DIM];    // (b,cam,q,c)
__device__ float g_kf    [(long)NB*NCAM*PK*DIM];     // (b,cam,kk,c)
__device__ float g_vf    [(long)NB*NCAM*PK*DIM];
__device__ float g_addq  [(long)NB*HWQ*DIM];
__device__ float g_scores[(long)NB*NHEAD*HWQ*NKEY];  // (b,m,q, cam*625+kk)  ~600MB
__device__ float g_attno [(long)NB*HWQ*ND];          // (b,q, cam*256+m*32+j)
__device__ float g_lnbuf [(long)NB*HWQ*ND];
__device__ float g_xbuf  [(long)NB*HWQ*DIM];
__device__ float g_h1    [(long)NB*HWQ*2*DIM];
__device__ float g_tbuf  [(long)NB*HWQ*DIM];

// ---------------- helpers ----------------
__device__ __forceinline__ float warpRedSum(float v){
    #pragma unroll
    for (int o=16;o;o>>=1) v += __shfl_xor_sync(0xffffffffu, v, o);
    return v;
}
__device__ __forceinline__ float warpRedMax(float v){
    #pragma unroll
    for (int o=16;o;o>>=1) v = fmaxf(v, __shfl_xor_sync(0xffffffffu, v, o));
    return v;
}

// ---------------- transpose q: (b,cam,c,p) -> (b,p,cam*256+c) ----------------
__global__ void transpose_q_kernel(const float* __restrict__ q, float* __restrict__ qT){
    __shared__ float tile[32][33];
    int bn  = blockIdx.z;           // b*6+cam
    int b   = bn / NCAM, cam = bn % NCAM;
    int p0  = blockIdx.x * 32;
    int c0  = blockIdx.y * 32;
    int tx  = threadIdx.x, ty = threadIdx.y;   // 32 x 8
    #pragma unroll
    for (int i = ty; i < 32; i += 8){
        int c = c0 + i, p = p0 + tx;
        float v = 0.f;
        if (p < HWQ) v = q[((long)bn*DIM + c)*HWQ + p];
        tile[i][tx] = v;
    }
    __syncthreads();
    #pragma unroll
    for (int i = ty; i < 32; i += 8){
        int p = p0 + i, c = c0 + tx;
        if (p < HWQ)
            qT[((long)(b*HWQ + p))*ND + cam*DIM + c] = tile[tx][i];
    }
}

// ---------------- 2x2 avg pool + transpose: (b,cam,c,50,50) -> (b,kk,cam*256+c) ----------------
__global__ void pool_kernel(const float* __restrict__ src, float* __restrict__ dst){
    long idx = (long)blockIdx.x * blockDim.x + threadIdx.x;
    const long total = (long)NB*NCAM*DIM*PK;
    if (idx >= total) return;
    int kk  = (int)(idx % PK);  long t = idx / PK;
    int c   = (int)(t % DIM);   t /= DIM;
    int cam = (int)(t % NCAM);
    int b   = (int)(t / NCAM);
    int i = kk / 25, j = kk % 25;
    const float* p = src + ((long)((b*NCAM+cam)*DIM + c))*HWQ + (2*i)*50 + 2*j;
    float v = 0.25f * (p[0] + p[1] + p[50] + p[51]);
    dst[((long)(b*PK + kk)*NCAM + cam)*DIM + c] = v;
}

// ---------------- generic batched strided SGEMM ----------------
// C[r,n] = alpha * sum_k A[r,k] * B[k,n] (+bias)(+gelu)(+Cadd)
// A[r,k] = A[r*lda + k]   (k contiguous)
// B: !bTrans -> B[k*ldb+n] ; bTrans -> B[n*ldb+k]
// batch z -> (i0,i1,i2): i2=z%D2, i1=(z/D2)%D1, i0=z/(D1*D2); offsets per component.
struct GemmParams {
    const float* A; const float* B; const float* bias; const float* Cadd; float* C;
    long lda, ldb, ldc, ldca;
    int  bTrans, M, N, K, gelu;
    float alpha;
    int  D1, D2;
    long a0,a1,a2, b0,b1,b2, c0,c1,c2, ca0,ca1,ca2;
};

template<int BM, int BN, int BK, int TM, int TN>
__global__ void sgemm_kernel(GemmParams p){
    constexpr int THREADS = (BM/TM)*(BN/TN);
    __shared__ float As[BK][BM+1];
    __shared__ float Bs[BK][BN+1];

    int z  = blockIdx.z;
    int i2 = z % p.D2; int tz = z / p.D2; int i1 = tz % p.D1; int i0 = tz / p.D1;
    const float* A = p.A + i0*p.a0 + i1*p.a1 + i2*p.a2;
    const float* B = p.B + i0*p.b0 + i1*p.b1 + i2*p.b2;
    float*       C = p.C + i0*p.c0 + i1*p.c1 + i2*p.c2;
    const float* Cadd = p.Cadd ? (p.Cadd + i0*p.ca0 + i1*p.ca1 + i2*p.ca2) : nullptr;

    int tid = threadIdx.x;
    int tx  = tid % (BN/TN);
    int ty  = tid / (BN/TN);
    int row0 = blockIdx.y * BM;
    int col0 = blockIdx.x * BN;

    float acc[TM][TN];
    #pragma unroll
    for (int i=0;i<TM;i++)
        #pragma unroll
        for (int j=0;j<TN;j++) acc[i][j] = 0.f;

    for (int k0 = 0; k0 < p.K; k0 += BK){
        // A tile: k-minor mapping, coalesced (k contiguous in memory)
        #pragma unroll
        for (int i = tid; i < BM*BK; i += THREADS){
            int r = i / BK, kk = i % BK;
            int gr = row0 + r, gk = k0 + kk;
            float v = 0.f;
            if (gr < p.M && gk < p.K) v = A[(long)gr*p.lda + gk];
            As[kk][r] = v;
        }
        if (!p.bTrans){
            #pragma unroll
            for (int i = tid; i < BK*BN; i += THREADS){
                int kk = i / BN, c = i % BN;
                int gk = k0 + kk, gc = col0 + c;
                float v = 0.f;
                if (gk < p.K && gc < p.N) v = B[(long)gk*p.ldb + gc];
                Bs[kk][c] = v;
            }
        } else {
            #pragma unroll
            for (int i = tid; i < BK*BN; i += THREADS){
                int c = i / BK, kk = i % BK;
                int gk = k0 + kk, gc = col0 + c;
                float v = 0.f;
                if (gk < p.K && gc < p.N) v = B[(long)gc*p.ldb + gk];
                Bs[kk][c] = v;
            }
        }
        __syncthreads();
        #pragma unroll
        for (int kk = 0; kk < BK; kk++){
            float ra[TM], rb[TN];
            #pragma unroll
            for (int i=0;i<TM;i++) ra[i] = As[kk][ty*TM+i];
            #pragma unroll
            for (int j=0;j<TN;j++) rb[j] = Bs[kk][tx*TN+j];
            #pragma unroll
            for (int i=0;i<TM;i++)
                #pragma unroll
                for (int j=0;j<TN;j++) acc[i][j] += ra[i]*rb[j];
        }
        __syncthreads();
    }
    #pragma unroll
    for (int i=0;i<TM;i++){
        int r = row0 + ty*TM + i;
        if (r >= p.M) continue;
        #pragma unroll
        for (int j=0;j<TN;j++){
            int c = col0 + tx*TN + j;
            if (c >= p.N) continue;
            float v = acc[i][j] * p.alpha;
            if (p.bias) v += p.bias[c];
            if (p.gelu) v = v * normcdff(v);   // exact GELU
            if (Cadd)   v += Cadd[(long)r*p.ldca + c];
            C[(long)r*p.ldc + c] = v;
        }
    }
}

// ---------------- softmax over 3750 keys ----------------
__global__ void softmax_kernel(float* __restrict__ s){
    __shared__ float sh[8];
    __shared__ float bval;
    long row = blockIdx.x;
    float* p = s + row * (long)NKEY;
    int tid = threadIdx.x;   // 256
    float vals[15];
    float mx = -1e30f;
    #pragma unroll
    for (int i=0;i<15;i++){
        int idx = tid + i*256;
        float v = (idx < NKEY) ? p[idx] : -1e30f;
        vals[i] = v; mx = fmaxf(mx, v);
    }
    mx = warpRedMax(mx);
    if ((tid & 31) == 0) sh[tid>>5] = mx;
    __syncthreads();
    if (tid == 0){ float m = sh[0]; for (int i=1;i<8;i++) m = fmaxf(m, sh[i]); bval = m; }
    __syncthreads();
    mx = bval;
    float sum = 0.f;
    #pragma unroll
    for (int i=0;i<15;i++){
        int idx = tid + i*256;
        float e = (idx < NKEY) ? expf(vals[i] - mx) : 0.f;
        vals[i] = e; sum += e;
    }
    sum = warpRedSum(sum);
    if ((tid & 31) == 0) sh[tid>>5] = sum;
    __syncthreads();
    if (tid == 0){ float t = 0.f; for (int i=0;i<8;i++) t += sh[i]; bval = t; }
    __syncthreads();
    float inv = 1.f / bval;
    #pragma unroll
    for (int i=0;i<15;i++){
        int idx = tid + i*256;
        if (idx < NKEY) p[idx] = vals[i] * inv;
    }
}

// ---------------- layernorm over 1536 ----------------
__global__ void ln1536_kernel(const float* __restrict__ x, const float* __restrict__ g,
                              const float* __restrict__ b, float* __restrict__ y){
    __shared__ float sh[8];
    __shared__ float bmu, brs;
    long row = blockIdx.x;
    const float* p = x + row * (long)ND;
    int tid = threadIdx.x;   // 256
    float vals[6]; float s = 0.f;
    #pragma unroll
    for (int i=0;i<6;i++){ vals[i] = p[tid + i*256]; s += vals[i]; }
    s = warpRedSum(s);
    if ((tid & 31) == 0) sh[tid>>5] = s;
    __syncthreads();
    if (tid == 0){ float t=0.f; for (int i=0;i<8;i++) t += sh[i]; bmu = t / (float)ND; }
    __syncthreads();
    float mu = bmu, vs = 0.f;
    #pragma unroll
    for (int i=0;i<6;i++){ float d = vals[i]-mu; vs += d*d; }
    vs = warpRedSum(vs);
    if ((tid & 31) == 0) sh[tid>>5] = vs;
    __syncthreads();
    if (tid == 0){ float t=0.f; for (int i=0;i<8;i++) t += sh[i]; brs = rsqrtf(t/(float)ND + 1e-5f); }
    __syncthreads();
    float rs = brs;
    float* q = y + row * (long)ND;
    #pragma unroll
    for (int i=0;i<6;i++){ int c = tid + i*256; q[c] = (vals[i]-mu)*rs*g[c] + b[c]; }
}

// ---------------- final: x + LN(t) then transpose to (B,d,H,W) ----------------
__global__ void final_kernel(const float* __restrict__ t, const float* __restrict__ x,
                             const float* __restrict__ g, const float* __restrict__ bb,
                             float* __restrict__ out){
    __shared__ float sh[8];
    __shared__ float bmu, brs;
    long row = blockIdx.x;          // b*2500 + p
    int c = threadIdx.x;            // 256
    float v = t[row*(long)DIM + c];
    float s = warpRedSum(v);
    if ((c & 31) == 0) sh[c>>5] = s;
    __syncthreads();
    if (c == 0){ float m=0.f; for (int i=0;i<8;i++) m += sh[i]; bmu = m / (float)DIM; }
    __syncthreads();
    float mu = bmu;
    float d = v - mu;
    float vs = warpRedSum(d*d);
    if ((c & 31) == 0) sh[c>>5] = vs;
    __syncthreads();
    if (c == 0){ float m=0.f; for (int i=0;i<8;i++) m += sh[i]; brs = rsqrtf(m/(float)DIM + 1e-5f); }
    __syncthreads();
    float y = d * brs * g[c] + bb[c] + x[row*(long)DIM + c];
    int b = (int)(row / HWQ), p = (int)(row % HWQ);
    out[((long)(b*DIM + c))*HWQ + p] = y;
}

// ---------------- host ----------------
static float* sym(const void* symbol){
    void* p = nullptr;
    cudaGetSymbolAddress(&p, symbol);
    return (float*)p;
}

static GemmParams zeroP(){ GemmParams p; memset(&p, 0, sizeof(p)); p.alpha = 1.f; p.D1 = 1; p.D2 = 1; return p; }

static void launch_main(const GemmParams& p, int batches){
    dim3 grid((p.N+63)/64, (p.M+127)/128, batches);
    sgemm_kernel<128,64,16,8,4><<<grid, 256>>>(p);
}
static void launch_pv(const GemmParams& p, int batches){
    dim3 grid((p.N+31)/32, (p.M+63)/64, batches);
    sgemm_kernel<64,32,32,4,2><<<grid, 256>>>(p);
}

extern "C" void kernel_launch(void* const* d_in, const int* in_sizes, int n_in,
                              void* d_out, int out_size){
    const float* q     = (const float*)d_in[0];
    const float* k     = (const float*)d_in[1];
    const float* v     = (const float*)d_in[2];
    const float* Wq    = (const float*)d_in[3];
    const float* bq    = (const float*)d_in[4];
    const float* Wk    = (const float*)d_in[5];
    const float* bk    = (const float*)d_in[6];
    const float* Wv    = (const float*)d_in[7];
    const float* bv    = (const float*)d_in[8];
    const float* Wproj = (const float*)d_in[9];
    const float* bproj = (const float*)d_in[10];
    const float* Waddq = (const float*)d_in[11];
    const float* baddq = (const float*)d_in[12];
    const float* W1    = (const float*)d_in[13];
    const float* b1    = (const float*)d_in[14];
    const float* W2    = (const float*)d_in[15];
    const float* b2    = (const float*)d_in[16];
    const float* g_pre = (const float*)d_in[17];
    const float* b_pre = (const float*)d_in[18];
    const float* g_nrm = (const float*)d_in[19];
    const float* b_nrm = (const float*)d_in[20];
    float* out = (float*)d_out;

    float* qT    = sym(g_qT);
    float* kpool = sym(g_kpool);
    float* vpool = sym(g_vpool);
    float* qf    = sym(g_qf);
    float* kf    = sym(g_kf);
    float* vf    = sym(g_vf);
    float* addq  = sym(g_addq);
    float* sc    = sym(g_scores);
    float* ao    = sym(g_attno);
    float* lnb   = sym(g_lnbuf);
    float* xb    = sym(g_xbuf);
    float* h1    = sym(g_h1);
    float* tb    = sym(g_tbuf);

    // 1) transpose q -> (b,p,nd)
    {
        dim3 grid((HWQ+31)/32, DIM/32, NB*NCAM);
        transpose_q_kernel<<<grid, dim3(32,8)>>>(q, qT);
    }
    // 2) pool k, v -> (b,kk,nd)
    {
        long total = (long)NB*NCAM*DIM*PK;
        int blocks = (int)((total + 255) / 256);
        pool_kernel<<<blocks, 256>>>(k, kpool);
        pool_kernel<<<blocks, 256>>>(v, vpool);
    }
    // 3) add_q = qT @ Waddq + baddq   (M=5000, K=1536, N=256)
    {
        GemmParams p = zeroP();
        p.A = qT; p.lda = ND; p.B = Waddq; p.ldb = DIM; p.bias = baddq;
        p.C = addq; p.ldc = DIM; p.M = NB*HWQ; p.N = DIM; p.K = ND;
        launch_main(p, 1);
    }
    // 4) qf: per (b,cam): qT slice @ Wq + bq
    {
        GemmParams p = zeroP();
        p.A = qT; p.lda = ND; p.a0 = (long)HWQ*ND; p.a1 = DIM;
        p.B = Wq; p.ldb = DIM; p.bias = bq;
        p.C = qf; p.ldc = DIM; p.c0 = (long)NCAM*HWQ*DIM; p.c1 = (long)HWQ*DIM;
        p.M = HWQ; p.N = DIM; p.K = DIM; p.D1 = NCAM; p.D2 = 1;
        launch_main(p, NB*NCAM);
    }
    // 5) kf, vf: per (b,cam): kpool slice @ Wk + bk
    {
        GemmParams p = zeroP();
        p.A = kpool; p.lda = ND; p.a0 = (long)PK*ND; p.a1 = DIM;
        p.B = Wk; p.ldb = DIM; p.bias = bk;
        p.C = kf; p.ldc = DIM; p.c0 = (long)NCAM*PK*DIM; p.c1 = (long)PK*DIM;
        p.M = PK; p.N = DIM; p.K = DIM; p.D1 = NCAM; p.D2 = 1;
        launch_main(p, NB*NCAM);
        p.A = vpool; p.B = Wv; p.bias = bv; p.C = vf;
        launch_main(p, NB*NCAM);
    }
    // 6) scores: per (b,m,cam): Q(2500x32) @ K^T(32x625), scaled
    {
        GemmParams p = zeroP();
        p.A = qf; p.lda = DIM;
        p.a0 = (long)NCAM*HWQ*DIM; p.a1 = DH; p.a2 = (long)HWQ*DIM;
        p.B = kf; p.ldb = DIM; p.bTrans = 1;
        p.b0 = (long)NCAM*PK*DIM;  p.b1 = DH; p.b2 = (long)PK*DIM;
        p.C = sc; p.ldc = NKEY;
        p.c0 = (long)NHEAD*HWQ*NKEY; p.c1 = (long)HWQ*NKEY; p.c2 = PK;
        p.M = HWQ; p.N = PK; p.K = DH;
        p.alpha = 0.17677669529663689f;  // 1/sqrt(32)
        p.D1 = NHEAD; p.D2 = NCAM;
        launch_main(p, NB*NHEAD*NCAM);
    }
    // 7) softmax over 3750
    softmax_kernel<<<NB*NHEAD*HWQ, 256>>>(sc);
    // 8) out = P @ V per (b,m,cam): 2500x625 @ 625x32
    {
        GemmParams p = zeroP();
        p.A = sc; p.lda = NKEY;
        p.a0 = (long)NHEAD*HWQ*NKEY; p.a1 = (long)HWQ*NKEY; p.a2 = PK;
        p.B = vf; p.ldb = DIM;
        p.b0 = (long)NCAM*PK*DIM; p.b1 = DH; p.b2 = (long)PK*DIM;
        p.C = ao; p.ldc = ND;
        p.c0 = (long)HWQ*ND; p.c1 = DH; p.c2 = DIM;
        p.M = HWQ; p.N = DH; p.K = PK;
        p.D1 = NHEAD; p.D2 = NCAM;
        launch_pv(p, NB*NHEAD*NCAM);
    }
    // 9) pre-layernorm over 1536
    ln1536_kernel<<<NB*HWQ, 256>>>(ao, g_pre, b_pre, lnb);
    // 10) x = LN(out) @ Wproj + bproj + add_q
    {
        GemmParams p = zeroP();
        p.A = lnb; p.lda = ND; p.B = Wproj; p.ldb = DIM; p.bias = bproj;
        p.Cadd = addq; p.ldca = DIM;
        p.C = xb; p.ldc = DIM; p.M = NB*HWQ; p.N = DIM; p.K = ND;
        launch_main(p, 1);
    }
    // 11) h1 = gelu(x @ W1 + b1)
    {
        GemmParams p = zeroP();
        p.A = xb; p.lda = DIM; p.B = W1; p.ldb = 2*DIM; p.bias = b1; p.gelu = 1;
        p.C = h1; p.ldc = 2*DIM; p.M = NB*HWQ; p.N = 2*DIM; p.K = DIM;
        launch_main(p, 1);
    }
    // 12) t = h1 @ W2 + b2
    {
        GemmParams p = zeroP();
        p.A = h1; p.lda = 2*DIM; p.B = W2; p.ldb = DIM; p.bias = b2;
        p.C = tb; p.ldc = DIM; p.M = NB*HWQ; p.N = DIM; p.K = 2*DIM;
        launch_main(p, 1);
    }
    // 13) out = transpose(x + LN(t))
    final_kernel<<<NB*HWQ, 256>>>(tb, xb, g_nrm, b_nrm, out);
}

// round 2
// speedup vs baseline: 1.7238x; 1.7238x over previous
#include <cuda_runtime.h>
#include <math.h>

#define NB    2
#define NCAM  6
#define DIM   256
#define HWQ   2500
#define PK    625
#define NHEAD 8
#define DH    32
#define ND    1536

typedef unsigned long long u64;

// ---------------- f32x2 packed math (Blackwell) ----------------
__device__ __forceinline__ u64 ffma2(u64 a, u64 b, u64 c){
    u64 d; asm("fma.rn.f32x2 %0, %1, %2, %3;" : "=l"(d) : "l"(a), "l"(b), "l"(c)); return d;
}
__device__ __forceinline__ u64 fmul2(u64 a, u64 b){
    u64 d; asm("mul.rn.f32x2 %0, %1, %2;" : "=l"(d) : "l"(a), "l"(b)); return d;
}
__device__ __forceinline__ u64 pack2(float x, float y){
    u64 d; asm("mov.b64 %0, {%1, %2};" : "=l"(d) : "f"(x), "f"(y)); return d;
}
__device__ __forceinline__ float2 unpack2(u64 v){
    float2 r; asm("mov.b64 {%0, %1}, %2;" : "=f"(r.x), "=f"(r.y) : "l"(v)); return r;
}

// ---------------- scratch ----------------
__device__ float g_qT    [(long)NB*HWQ*ND];
__device__ float g_kpool [(long)NB*PK*ND];
__device__ float g_vpool [(long)NB*PK*ND];
__device__ float g_qf    [(long)NB*NCAM*HWQ*DIM];
__device__ float g_kf    [(long)NB*NCAM*PK*DIM];
__device__ float g_vf    [(long)NB*NCAM*PK*DIM];
__device__ float g_addq  [(long)NB*HWQ*DIM];
__device__ float g_attno [(long)NB*HWQ*ND];
__device__ float g_lnbuf [(long)NB*HWQ*ND];
__device__ float g_xbuf  [(long)NB*HWQ*DIM];
__device__ float g_h1    [(long)NB*HWQ*2*DIM];
__device__ float g_tbuf  [(long)NB*HWQ*DIM];

__device__ __forceinline__ float warpRedSum(float v){
    #pragma unroll
    for (int o=16;o;o>>=1) v += __shfl_xor_sync(0xffffffffu, v, o);
    return v;
}

// ---------------- transpose q: (b,cam,c,p) -> (b,p,cam*256+c) ----------------
__global__ void transpose_q_kernel(const float* __restrict__ q, float* __restrict__ qT){
    __shared__ float tile[32][33];
    int bn  = blockIdx.z;
    int b   = bn / NCAM, cam = bn % NCAM;
    int p0  = blockIdx.x * 32;
    int c0  = blockIdx.y * 32;
    int tx  = threadIdx.x, ty = threadIdx.y;
    #pragma unroll
    for (int i = ty; i < 32; i += 8){
        int c = c0 + i, p = p0 + tx;
        float v = 0.f;
        if (p < HWQ) v = q[((long)bn*DIM + c)*HWQ + p];
        tile[i][tx] = v;
    }
    __syncthreads();
    #pragma unroll
    for (int i = ty; i < 32; i += 8){
        int p = p0 + i, c = c0 + tx;
        if (p < HWQ)
            qT[((long)(b*HWQ + p))*ND + cam*DIM + c] = tile[tx][i];
    }
}

// ---------------- 2x2 pool + transpose ----------------
__global__ void pool_kernel(const float* __restrict__ src, float* __restrict__ dst){
    long idx = (long)blockIdx.x * blockDim.x + threadIdx.x;
    const long total = (long)NB*NCAM*DIM*PK;
    if (idx >= total) return;
    int kk  = (int)(idx % PK);  long t = idx / PK;
    int c   = (int)(t % DIM);   t /= DIM;
    int cam = (int)(t % NCAM);
    int b   = (int)(t / NCAM);
    int i = kk / 25, j = kk % 25;
    const float* p = src + ((long)((b*NCAM+cam)*DIM + c))*HWQ + (2*i)*50 + 2*j;
    float v = 0.25f * (p[0] + p[1] + p[50] + p[51]);
    dst[((long)(b*PK + kk)*NCAM + cam)*DIM + c] = v;
}

// ---------------- dense GEMM, f32x2, double-buffered ----------------
// C = A(MxK) @ B(KxN) (+bias)(+gelu)(+Cadd).  K%16==0, N%64==0, lda/ldb/ldc%4==0.
struct GemmP {
    const float* A; const float* B; const float* bias; const float* Cadd; float* C;
    int lda, ldb, ldc, ldca;
    int M, N, K, gelu, D1;
    long a0, a1, c0, c1;
};

__global__ __launch_bounds__(256,2) void gemm_f32x2(GemmP p){
    __shared__ float As[2][16][128];
    __shared__ float Bs[2][16][64];
    int z = blockIdx.z;
    int i0 = z / p.D1, i1 = z % p.D1;
    const float* A = p.A + i0*p.a0 + i1*p.a1;
    float* C = p.C + i0*p.c0 + i1*p.c1;
    const float* B = p.B;

    int tid = threadIdx.x;
    int tx = tid & 15, ty = tid >> 4;
    int row0 = blockIdx.y * 128, col0 = blockIdx.x * 64;

    int ar = tid >> 1;           // A row within tile (0..127)
    int ac = (tid & 1) * 8;      // A k-chunk (0 or 8)
    int bk = tid >> 4;           // B k row
    int bc = (tid & 15) * 4;     // B col chunk

    u64 acc[8][2];
    #pragma unroll
    for (int i=0;i<8;i++){ acc[i][0]=0ULL; acc[i][1]=0ULL; }

    float4 ra0, ra1, rb;
    const float4 z4 = make_float4(0.f,0.f,0.f,0.f);

    int nt = p.K / 16;
    // prefetch tile 0
    {
        if (row0 + ar < p.M){
            const float* pa = A + (long)(row0+ar)*p.lda + ac;
            ra0 = *(const float4*)pa; ra1 = *(const float4*)(pa+4);
        } else { ra0 = z4; ra1 = z4; }
        rb = *(const float4*)(B + (long)bk*p.ldb + col0 + bc);
    }
    // stage 0
    {
        As[0][ac+0][ar]=ra0.x; As[0][ac+1][ar]=ra0.y; As[0][ac+2][ar]=ra0.z; As[0][ac+3][ar]=ra0.w;
        As[0][ac+4][ar]=ra1.x; As[0][ac+5][ar]=ra1.y; As[0][ac+6][ar]=ra1.z; As[0][ac+7][ar]=ra1.w;
        *(float4*)&Bs[0][bk][bc] = rb;
    }
    __syncthreads();
    int cur = 0;
    for (int t=0; t<nt; t++){
        if (t+1 < nt){
            int k0 = (t+1)*16;
            if (row0 + ar < p.M){
                const float* pa = A + (long)(row0+ar)*p.lda + k0 + ac;
                ra0 = *(const float4*)pa; ra1 = *(const float4*)(pa+4);
            } else { ra0 = z4; ra1 = z4; }
            rb = *(const float4*)(B + (long)(k0+bk)*p.ldb + col0 + bc);
        }
        #pragma unroll
        for (int kk=0; kk<16; kk++){
            float4 a0 = *(const float4*)&As[cur][kk][ty*8];
            float4 a1 = *(const float4*)&As[cur][kk][ty*8+4];
            ulonglong2 bv = *(const ulonglong2*)&Bs[cur][kk][tx*4];
            u64 ap;
            ap = pack2(a0.x,a0.x); acc[0][0]=ffma2(ap,bv.x,acc[0][0]); acc[0][1]=ffma2(ap,bv.y,acc[0][1]);
            ap = pack2(a0.y,a0.y); acc[1][0]=ffma2(ap,bv.x,acc[1][0]); acc[1][1]=ffma2(ap,bv.y,acc[1][1]);
            ap = pack2(a0.z,a0.z); acc[2][0]=ffma2(ap,bv.x,acc[2][0]); acc[2][1]=ffma2(ap,bv.y,acc[2][1]);
            ap = pack2(a0.w,a0.w); acc[3][0]=ffma2(ap,bv.x,acc[3][0]); acc[3][1]=ffma2(ap,bv.y,acc[3][1]);
            ap = pack2(a1.x,a1.x); acc[4][0]=ffma2(ap,bv.x,acc[4][0]); acc[4][1]=ffma2(ap,bv.y,acc[4][1]);
            ap = pack2(a1.y,a1.y); acc[5][0]=ffma2(ap,bv.x,acc[5][0]); acc[5][1]=ffma2(ap,bv.y,acc[5][1]);
            ap = pack2(a1.z,a1.z); acc[6][0]=ffma2(ap,bv.x,acc[6][0]); acc[6][1]=ffma2(ap,bv.y,acc[6][1]);
            ap = pack2(a1.w,a1.w); acc[7][0]=ffma2(ap,bv.x,acc[7][0]); acc[7][1]=ffma2(ap,bv.y,acc[7][1]);
        }
        if (t+1 < nt){
            int nb = cur ^ 1;
            As[nb][ac+0][ar]=ra0.x; As[nb][ac+1][ar]=ra0.y; As[nb][ac+2][ar]=ra0.z; As[nb][ac+3][ar]=ra0.w;
            As[nb][ac+4][ar]=ra1.x; As[nb][ac+5][ar]=ra1.y; As[nb][ac+6][ar]=ra1.z; As[nb][ac+7][ar]=ra1.w;
            *(float4*)&Bs[nb][bk][bc] = rb;
            __syncthreads();
            cur = nb;
        }
    }
    #pragma unroll
    for (int i=0;i<8;i++){
        int r = row0 + ty*8 + i;
        if (r >= p.M) continue;
        float2 v0 = unpack2(acc[i][0]), v1 = unpack2(acc[i][1]);
        float4 o = make_float4(v0.x, v0.y, v1.x, v1.y);
        int c = col0 + tx*4;
        if (p.bias){
            float4 bb = *(const float4*)(p.bias + c);
            o.x+=bb.x; o.y+=bb.y; o.z+=bb.z; o.w+=bb.w;
        }
        if (p.gelu){
            o.x *= normcdff(o.x); o.y *= normcdff(o.y);
            o.z *= normcdff(o.z); o.w *= normcdff(o.w);
        }
        if (p.Cadd){
            const float* ca = p.Cadd + i0*p.c0 + i1*p.c1;  // Cadd shares C's batch layout
            float4 av = *(const float4*)(ca + (long)r*p.ldca + c);
            o.x+=av.x; o.y+=av.y; o.z+=av.z; o.w+=av.w;
        }
        *(float4*)(C + (long)r*p.ldc + c) = o;
    }
}

// ---------------- fused flash attention ----------------
// grid: x = q-tile (ceil(2500/64)), y = b*8+m. 256 threads (16x16).
// Joint softmax over 6 cams x 625 keys; per-cam PV accumulators.
__global__ __launch_bounds__(256,2) void flash_kernel(
    const float* __restrict__ qf, const float* __restrict__ kf,
    const float* __restrict__ vf, float* __restrict__ ao)
{
    __shared__ float Qs[64][32];
    __shared__ float Ks[64][36];
    __shared__ float Vt[32][68];
    __shared__ float Ps[64][64];

    int zz = blockIdx.y; int b = zz >> 3, m = zz & 7;
    int q0 = blockIdx.x * 64;
    int tid = threadIdx.x, tx = tid & 15, ty = tid >> 4;
    const float scale = 0.17677669529663689f;
    const float4 z4 = make_float4(0.f,0.f,0.f,0.f);

    float fO[6][4][2];
    #pragma unroll
    for (int c=0;c<6;c++)
        #pragma unroll
        for (int i=0;i<4;i++){ fO[c][i][0]=0.f; fO[c][i][1]=0.f; }
    float mrow[4] = {-1e30f,-1e30f,-1e30f,-1e30f};
    float lrow[4] = {0.f,0.f,0.f,0.f};

    for (int cam=0; cam<6; cam++){
        u64 accA[4], accB[4];
        #pragma unroll
        for (int i=0;i<4;i++){ accA[i]=0ULL; accB[i]=0ULL; }
        const float* qbase = qf + ((long)(b*NCAM+cam)*HWQ)*DIM + m*DH;
        const float* kbase = kf + ((long)(b*NCAM+cam)*PK)*DIM + m*DH;
        const float* vbase = vf + ((long)(b*NCAM+cam)*PK)*DIM + m*DH;

        for (int kt=0; kt<10; kt++){
            int kk0 = kt*64;
            __syncthreads();   // prior PV (and prior cam's Q use) complete
            if (kt == 0){
                #pragma unroll
                for (int t=0;t<2;t++){
                    int idx = tid + t*256;
                    int r = idx>>3, c4 = (idx&7)*4;
                    float4 v = z4;
                    if (q0+r < HWQ) v = *(const float4*)(qbase + (long)(q0+r)*DIM + c4);
                    v.x*=scale; v.y*=scale; v.z*=scale; v.w*=scale;
                    *(float4*)&Qs[r][c4] = v;
                }
            }
            #pragma unroll
            for (int t=0;t<2;t++){
                int idx = tid + t*256;
                int r = idx>>3, c4 = (idx&7)*4;
                float4 kv = z4, vv = z4;
                if (kk0 + r < PK){
                    kv = *(const float4*)(kbase + (long)(kk0+r)*DIM + c4);
                    vv = *(const float4*)(vbase + (long)(kk0+r)*DIM + c4);
                }
                *(float4*)&Ks[r][c4] = kv;
                Vt[c4+0][r]=vv.x; Vt[c4+1][r]=vv.y; Vt[c4+2][r]=vv.z; Vt[c4+3][r]=vv.w;
            }
            __syncthreads();

            // S = Qs . Ks^T   rows: ty*4+i, key cols: tx + 16*j
            u64 sacc[4][4];
            #pragma unroll
            for (int i=0;i<4;i++)
                #pragma unroll
                for (int j=0;j<4;j++) sacc[i][j]=0ULL;
            #pragma unroll
            for (int c4=0;c4<8;c4++){
                ulonglong2 qv[4], kv[4];
                #pragma unroll
                for (int i=0;i<4;i++) qv[i] = *(const ulonglong2*)&Qs[ty*4+i][c4*4];
                #pragma unroll
                for (int j=0;j<4;j++) kv[j] = *(const ulonglong2*)&Ks[tx+16*j][c4*4];
                #pragma unroll
                for (int i=0;i<4;i++)
                    #pragma unroll
                    for (int j=0;j<4;j++){
                        sacc[i][j]=ffma2(qv[i].x,kv[j].x,sacc[i][j]);
                        sacc[i][j]=ffma2(qv[i].y,kv[j].y,sacc[i][j]);
                    }
            }
            // online softmax update
            #pragma unroll
            for (int i=0;i<4;i++){
                float s_[4];
                float tmax = -1e30f;
                #pragma unroll
                for (int j=0;j<4;j++){
                    float2 t2 = unpack2(sacc[i][j]);
                    float s = t2.x + t2.y;
                    if (kk0 + tx + 16*j >= PK) s = -1e30f;
                    s_[j] = s; tmax = fmaxf(tmax, s);
                }
                #pragma unroll
                for (int off=1; off<16; off<<=1)
                    tmax = fmaxf(tmax, __shfl_xor_sync(0xffffffffu, tmax, off));
                float mnew = fmaxf(mrow[i], tmax);
                float corr = __expf(mrow[i] - mnew);
                float rsum = 0.f;
                #pragma unroll
                for (int j=0;j<4;j++){
                    float pv = __expf(s_[j] - mnew);
                    rsum += pv;
                    Ps[ty*4+i][tx+16*j] = pv;
                }
                #pragma unroll
                for (int off=1; off<16; off<<=1)
                    rsum += __shfl_xor_sync(0xffffffffu, rsum, off);
                lrow[i] = lrow[i]*corr + rsum;
                mrow[i] = mnew;
                u64 cp = pack2(corr, corr);
                accA[i] = fmul2(accA[i], cp);
                accB[i] = fmul2(accB[i], cp);
                #pragma unroll
                for (int c=0;c<6;c++){ fO[c][i][0]*=corr; fO[c][i][1]*=corr; }
            }
            __syncthreads();   // Ps visible; Vt stable until next tile load

            // O += P . V  (k packed in f32x2 lanes; V transposed)
            #pragma unroll
            for (int k4=0;k4<16;k4++){
                ulonglong2 va = *(const ulonglong2*)&Vt[tx][k4*4];
                ulonglong2 vb = *(const ulonglong2*)&Vt[tx+16][k4*4];
                #pragma unroll
                for (int i=0;i<4;i++){
                    ulonglong2 pp = *(const ulonglong2*)&Ps[ty*4+i][k4*4];
                    accA[i]=ffma2(pp.x,va.x,accA[i]); accA[i]=ffma2(pp.y,va.y,accA[i]);
                    accB[i]=ffma2(pp.x,vb.x,accB[i]); accB[i]=ffma2(pp.y,vb.y,accB[i]);
                }
            }
        }
        // fold this cam's accumulators (horizontal add of k-parity lanes)
        #pragma unroll
        for (int i=0;i<4;i++){
            float2 a = unpack2(accA[i]); fO[cam][i][0] += a.x + a.y;
            float2 v2 = unpack2(accB[i]); fO[cam][i][1] += v2.x + v2.y;
        }
    }
    // normalize + store: ao[b, q, cam*256 + m*32 + col]
    #pragma unroll
    for (int i=0;i<4;i++){
        int q = q0 + ty*4 + i;
        if (q >= HWQ) continue;
        float inv = 1.f / lrow[i];
        long rowoff = ((long)b*HWQ + q)*ND + m*DH;
        #pragma unroll
        for (int c=0;c<6;c++){
            ao[rowoff + c*DIM + tx]      = fO[c][i][0]*inv;
            ao[rowoff + c*DIM + tx+16]   = fO[c][i][1]*inv;
        }
    }
}

// ---------------- layernorm over 1536 ----------------
__global__ void ln1536_kernel(const float* __restrict__ x, const float* __restrict__ g,
                              const float* __restrict__ b, float* __restrict__ y){
    __shared__ float sh[8];
    __shared__ float bmu, brs;
    long row = blockIdx.x;
    const float* p = x + row * (long)ND;
    int tid = threadIdx.x;
    float vals[6]; float s = 0.f;
    #pragma unroll
    for (int i=0;i<6;i++){ vals[i] = p[tid + i*256]; s += vals[i]; }
    s = warpRedSum(s);
    if ((tid & 31) == 0) sh[tid>>5] = s;
    __syncthreads();
    if (tid == 0){ float t=0.f; for (int i=0;i<8;i++) t += sh[i]; bmu = t / (float)ND; }
    __syncthreads();
    float mu = bmu, vs = 0.f;
    #pragma unroll
    for (int i=0;i<6;i++){ float d = vals[i]-mu; vs += d*d; }
    vs = warpRedSum(vs);
    if ((tid & 31) == 0) sh[tid>>5] = vs;
    __syncthreads();
    if (tid == 0){ float t=0.f; for (int i=0;i<8;i++) t += sh[i]; brs = rsqrtf(t/(float)ND + 1e-5f); }
    __syncthreads();
    float rs = brs;
    float* q = y + row * (long)ND;
    #pragma unroll
    for (int i=0;i<6;i++){ int c = tid + i*256; q[c] = (vals[i]-mu)*rs*g[c] + b[c]; }
}

// ---------------- final: x + LN(t), transpose to (B,d,H,W) ----------------
__global__ void final_kernel(const float* __restrict__ t, const float* __restrict__ x,
                             const float* __restrict__ g, const float* __restrict__ bb,
                             float* __restrict__ out){
    __shared__ float sh[8];
    __shared__ float bmu, brs;
    long row = blockIdx.x;
    int c = threadIdx.x;
    float v = t[row*(long)DIM + c];
    float s = warpRedSum(v);
    if ((c & 31) == 0) sh[c>>5] = s;
    __syncthreads();
    if (c == 0){ float m=0.f; for (int i=0;i<8;i++) m += sh[i]; bmu = m / (float)DIM; }
    __syncthreads();
    float mu = bmu;
    float d = v - mu;
    float vs = warpRedSum(d*d);
    if ((c & 31) == 0) sh[c>>5] = vs;
    __syncthreads();
    if (c == 0){ float m=0.f; for (int i=0;i<8;i++) m += sh[i]; brs = rsqrtf(m/(float)DIM + 1e-5f); }
    __syncthreads();
    float y = d * brs * g[c] + bb[c] + x[row*(long)DIM + c];
    int b = (int)(row / HWQ), p = (int)(row % HWQ);
    out[((long)(b*DIM + c))*HWQ + p] = y;
}

// ---------------- host ----------------
static float* sym(const void* symbol){
    void* p = nullptr;
    cudaGetSymbolAddress(&p, symbol);
    return (float*)p;
}

static GemmP zeroP(){ GemmP p; memset(&p, 0, sizeof(p)); p.D1 = 1; return p; }

static void launch_gemm(const GemmP& p, int batches){
    dim3 grid(p.N/64, (p.M+127)/128, batches);
    gemm_f32x2<<<grid, 256>>>(p);
}

extern "C" void kernel_launch(void* const* d_in, const int* in_sizes, int n_in,
                              void* d_out, int out_size){
    const float* q     = (const float*)d_in[0];
    const float* k     = (const float*)d_in[1];
    const float* v     = (const float*)d_in[2];
    const float* Wq    = (const float*)d_in[3];
    const float* bq    = (const float*)d_in[4];
    const float* Wk    = (const float*)d_in[5];
    const float* bk    = (const float*)d_in[6];
    const float* Wv    = (const float*)d_in[7];
    const float* bv    = (const float*)d_in[8];
    const float* Wproj = (const float*)d_in[9];
    const float* bproj = (const float*)d_in[10];
    const float* Waddq = (const float*)d_in[11];
    const float* baddq = (const float*)d_in[12];
    const float* W1    = (const float*)d_in[13];
    const float* b1    = (const float*)d_in[14];
    const float* W2    = (const float*)d_in[15];
    const float* b2    = (const float*)d_in[16];
    const float* g_pre = (const float*)d_in[17];
    const float* b_pre = (const float*)d_in[18];
    const float* g_nrm = (const float*)d_in[19];
    const float* b_nrm = (const float*)d_in[20];
    float* out = (float*)d_out;

    float* qT    = sym(g_qT);
    float* kpool = sym(g_kpool);
    float* vpool = sym(g_vpool);
    float* qf    = sym(g_qf);
    float* kf    = sym(g_kf);
    float* vf    = sym(g_vf);
    float* addq  = sym(g_addq);
    float* ao    = sym(g_attno);
    float* lnb   = sym(g_lnbuf);
    float* xb    = sym(g_xbuf);
    float* h1    = sym(g_h1);
    float* tb    = sym(g_tbuf);

    // 1) transpose q -> (b,p,nd)
    {
        dim3 grid((HWQ+31)/32, DIM/32, NB*NCAM);
        transpose_q_kernel<<<grid, dim3(32,8)>>>(q, qT);
    }
    // 2) pool k, v
    {
        long total = (long)NB*NCAM*DIM*PK;
        int blocks = (int)((total + 255) / 256);
        pool_kernel<<<blocks, 256>>>(k, kpool);
        pool_kernel<<<blocks, 256>>>(v, vpool);
    }
    // 3) add_q = qT @ Waddq + baddq
    {
        GemmP p = zeroP();
        p.A = qT; p.lda = ND; p.B = Waddq; p.ldb = DIM; p.bias = baddq;
        p.C = addq; p.ldc = DIM; p.M = NB*HWQ; p.N = DIM; p.K = ND;
        launch_gemm(p, 1);
    }
    // 4) qf per (b,cam)
    {
        GemmP p = zeroP();
        p.A = qT; p.lda = ND; p.a0 = (long)HWQ*ND; p.a1 = DIM;
        p.B = Wq; p.ldb = DIM; p.bias = bq;
        p.C = qf; p.ldc = DIM; p.c0 = (long)NCAM*HWQ*DIM; p.c1 = (long)HWQ*DIM;
        p.M = HWQ; p.N = DIM; p.K = DIM; p.D1 = NCAM;
        launch_gemm(p, NB*NCAM);
    }
    // 5) kf, vf per (b,cam)
    {
        GemmP p = zeroP();
        p.A = kpool; p.lda = ND; p.a0 = (long)PK*ND; p.a1 = DIM;
        p.B = Wk; p.ldb = DIM; p.bias = bk;
        p.C = kf; p.ldc = DIM; p.c0 = (long)NCAM*PK*DIM; p.c1 = (long)PK*DIM;
        p.M = PK; p.N = DIM; p.K = DIM; p.D1 = NCAM;
        launch_gemm(p, NB*NCAM);
        p.A = vpool; p.B = Wv; p.bias = bv; p.C = vf;
        launch_gemm(p, NB*NCAM);
    }
    // 6) fused flash attention -> ao (b,q,nd)
    {
        dim3 grid((HWQ+63)/64, NB*NHEAD);
        flash_kernel<<<grid, 256>>>(qf, kf, vf, ao);
    }
    // 7) pre-layernorm over 1536
    ln1536_kernel<<<NB*HWQ, 256>>>(ao, g_pre, b_pre, lnb);
    // 8) x = LN(out) @ Wproj + bproj + add_q
    {
        GemmP p = zeroP();
        p.A = lnb; p.lda = ND; p.B = Wproj; p.ldb = DIM; p.bias = bproj;
        p.Cadd = addq; p.ldca = DIM;
        p.C = xb; p.ldc = DIM; p.M = NB*HWQ; p.N = DIM; p.K = ND;
        launch_gemm(p, 1);
    }
    // 9) h1 = gelu(x @ W1 + b1)
    {
        GemmP p = zeroP();
        p.A = xb; p.lda = DIM; p.B = W1; p.ldb = 2*DIM; p.bias = b1; p.gelu = 1;
        p.C = h1; p.ldc = 2*DIM; p.M = NB*HWQ; p.N = 2*DIM; p.K = DIM;
        launch_gemm(p, 1);
    }
    // 10) t = h1 @ W2 + b2
    {
        GemmP p = zeroP();
        p.A = h1; p.lda = 2*DIM; p.B = W2; p.ldb = DIM; p.bias = b2;
        p.C = tb; p.ldc = DIM; p.M = NB*HWQ; p.N = DIM; p.K = 2*DIM;
        launch_gemm(p, 1);
    }
    // 11) out = transpose(x + LN(t))
    final_kernel<<<NB*HWQ, 256>>>(tb, xb, g_nrm, b_nrm, out);
}

// round 3
// speedup vs baseline: 2.1973x; 1.2747x over previous
#include <cuda_runtime.h>
#include <math.h>

#define NB    2
#define NCAM  6
#define DIM   256
#define HWQ   2500
#define PK    625
#define NHEAD 8
#define DH    32
#define ND    1536

typedef unsigned long long u64;

// ---------------- f32x2 packed math (Blackwell) ----------------
__device__ __forceinline__ u64 ffma2(u64 a, u64 b, u64 c){
    u64 d; asm("fma.rn.f32x2 %0, %1, %2, %3;" : "=l"(d) : "l"(a), "l"(b), "l"(c)); return d;
}
__device__ __forceinline__ u64 fmul2(u64 a, u64 b){
    u64 d; asm("mul.rn.f32x2 %0, %1, %2;" : "=l"(d) : "l"(a), "l"(b)); return d;
}
__device__ __forceinline__ u64 pack2(float x, float y){
    u64 d; asm("mov.b64 %0, {%1, %2};" : "=l"(d) : "f"(x), "f"(y)); return d;
}
__device__ __forceinline__ float2 unpack2(u64 v){
    float2 r; asm("mov.b64 {%0, %1}, %2;" : "=f"(r.x), "=f"(r.y) : "l"(v)); return r;
}

// ---------------- scratch ----------------
__device__ float g_qT    [(long)NB*HWQ*ND];
__device__ float g_kpool [(long)NB*PK*ND];
__device__ float g_vpool [(long)NB*PK*ND];
__device__ float g_qf    [(long)NB*NCAM*HWQ*DIM];
__device__ float g_kf    [(long)NB*NCAM*PK*DIM];
__device__ float g_vf    [(long)NB*NCAM*PK*DIM];
__device__ float g_attno [(long)NB*HWQ*ND];          // unnormalized per-cam partials
__device__ float g_fac   [(long)NB*HWQ*64];          // [0..47]=m_c per cam*8+m, [48..55]=m_fin, [56..63]=l
__device__ float g_lnbuf [(long)NB*HWQ*ND];
__device__ float g_xbuf  [(long)NB*HWQ*DIM];
__device__ float g_h1    [(long)NB*HWQ*2*DIM];
__device__ float g_part1 [(long)3*NB*HWQ*DIM];       // add_q split-K partials
__device__ float g_part2 [(long)3*NB*HWQ*DIM];       // proj split-K partials
__device__ float g_part3 [(long)2*NB*HWQ*DIM];       // ffn2 split-K partials

__device__ __forceinline__ float warpRedSum(float v){
    #pragma unroll
    for (int o=16;o;o>>=1) v += __shfl_xor_sync(0xffffffffu, v, o);
    return v;
}

// ---------------- transpose q: (b,cam,c,p) -> (b,p,cam*256+c) ----------------
__global__ void transpose_q_kernel(const float* __restrict__ q, float* __restrict__ qT){
    __shared__ float tile[32][33];
    int bn  = blockIdx.z;
    int b   = bn / NCAM, cam = bn % NCAM;
    int p0  = blockIdx.x * 32;
    int c0  = blockIdx.y * 32;
    int tx  = threadIdx.x, ty = threadIdx.y;
    #pragma unroll
    for (int i = ty; i < 32; i += 8){
        int c = c0 + i, p = p0 + tx;
        float v = 0.f;
        if (p < HWQ) v = q[((long)bn*DIM + c)*HWQ + p];
        tile[i][tx] = v;
    }
    __syncthreads();
    #pragma unroll
    for (int i = ty; i < 32; i += 8){
        int p = p0 + i, c = c0 + tx;
        if (p < HWQ)
            qT[((long)(b*HWQ + p))*ND + cam*DIM + c] = tile[tx][i];
    }
}

// ---------------- 2x2 pool + transpose ----------------
__global__ void pool_kernel(const float* __restrict__ src, float* __restrict__ dst){
    long idx = (long)blockIdx.x * blockDim.x + threadIdx.x;
    const long total = (long)NB*NCAM*DIM*PK;
    if (idx >= total) return;
    int kk  = (int)(idx % PK);  long t = idx / PK;
    int c   = (int)(t % DIM);   t /= DIM;
    int cam = (int)(t % NCAM);
    int b   = (int)(t / NCAM);
    int i = kk / 25, j = kk % 25;
    const float* p = src + ((long)((b*NCAM+cam)*DIM + c))*HWQ + (2*i)*50 + 2*j;
    float v = 0.25f * (p[0] + p[1] + p[50] + p[51]);
    dst[((long)(b*PK + kk)*NCAM + cam)*DIM + c] = v;
}

// ---------------- dense GEMM: 128 thr, BM128/BN64/BK16, 8x8/thread, split-K ----
struct GemmP {
    const float* A; const float* B; const float* bias; float* C;
    int lda, ldb, ldc;
    int M, N, K;            // K = per-split span
    int gelu, D1, SPLIT;
    long a0, a1, c0, c1, csplit;
};

__global__ __launch_bounds__(128,4) void gemm_tc(GemmP p){
    __shared__ float As[2][16][128];
    __shared__ float Bs[2][16][64];

    int z = blockIdx.z;
    int s = z % p.SPLIT; int zz = z / p.SPLIT;
    int i1 = zz % p.D1;  int i0 = zz / p.D1;
    const float* A = p.A + i0*p.a0 + i1*p.a1 + (long)s*p.K;
    const float* B = p.B + (long)s*p.K*p.ldb;
    float*       C = p.C + i0*p.c0 + i1*p.c1 + (long)s*p.csplit;

    int tid = threadIdx.x;
    int tx = tid & 7, ty = tid >> 3;
    int row0 = blockIdx.y*128, col0 = blockIdx.x*64;

    int arow = row0 + tid;
    int brow = tid >> 3;
    int bc0  = (tid & 7) * 2;                      // chunk ids bc0, bc0+1 (4-float chunks)
    int pb0  = (bc0 ^ (bc0 >> 3)) * 4;             // XOR swizzle kills quarter conflicts
    int pb1  = ((bc0+1) ^ ((bc0+1) >> 3)) * 4;

    u64 acc[8][4];
    #pragma unroll
    for (int i=0;i<8;i++)
        #pragma unroll
        for (int j=0;j<4;j++) acc[i][j] = 0ULL;

    const float4 z4 = make_float4(0.f,0.f,0.f,0.f);
    float4 ra[4], rb0, rb1;

    int nt = p.K / 16;
    // prefetch tile 0
    if (arow < p.M){
        const float* pa = A + (long)arow*p.lda;
        ra[0]=*(const float4*)pa; ra[1]=*(const float4*)(pa+4);
        ra[2]=*(const float4*)(pa+8); ra[3]=*(const float4*)(pa+12);
    } else { ra[0]=z4; ra[1]=z4; ra[2]=z4; ra[3]=z4; }
    {
        const float* pb = B + (long)brow*p.ldb + col0 + bc0*4;
        rb0 = *(const float4*)pb; rb1 = *(const float4*)(pb+4);
    }
    // stage 0
    {
        #pragma unroll
        for (int j=0;j<4;j++){
            As[0][j*4+0][tid]=ra[j].x; As[0][j*4+1][tid]=ra[j].y;
            As[0][j*4+2][tid]=ra[j].z; As[0][j*4+3][tid]=ra[j].w;
        }
        *(float4*)&Bs[0][brow][pb0] = rb0;
        *(float4*)&Bs[0][brow][pb1] = rb1;
    }
    __syncthreads();
    int cur = 0;
    for (int t=0; t<nt; t++){
        if (t+1 < nt){
            int k0 = (t+1)*16;
            if (arow < p.M){
                const float* pa = A + (long)arow*p.lda + k0;
                ra[0]=*(const float4*)pa; ra[1]=*(const float4*)(pa+4);
                ra[2]=*(const float4*)(pa+8); ra[3]=*(const float4*)(pa+12);
            } else { ra[0]=z4; ra[1]=z4; ra[2]=z4; ra[3]=z4; }
            const float* pb = B + (long)(k0+brow)*p.ldb + col0 + bc0*4;
            rb0 = *(const float4*)pb; rb1 = *(const float4*)(pb+4);
        }
        #pragma unroll
        for (int kk=0; kk<16; kk++){
            float4 a0 = *(const float4*)&As[cur][kk][ty*8];
            float4 a1 = *(const float4*)&As[cur][kk][ty*8+4];
            ulonglong2 b0 = *(const ulonglong2*)&Bs[cur][kk][pb0];
            ulonglong2 b1 = *(const ulonglong2*)&Bs[cur][kk][pb1];
            u64 ap;
            ap=pack2(a0.x,a0.x); acc[0][0]=ffma2(ap,b0.x,acc[0][0]); acc[0][1]=ffma2(ap,b0.y,acc[0][1]); acc[0][2]=ffma2(ap,b1.x,acc[0][2]); acc[0][3]=ffma2(ap,b1.y,acc[0][3]);
            ap=pack2(a0.y,a0.y); acc[1][0]=ffma2(ap,b0.x,acc[1][0]); acc[1][1]=ffma2(ap,b0.y,acc[1][1]); acc[1][2]=ffma2(ap,b1.x,acc[1][2]); acc[1][3]=ffma2(ap,b1.y,acc[1][3]);
            ap=pack2(a0.z,a0.z); acc[2][0]=ffma2(ap,b0.x,acc[2][0]); acc[2][1]=ffma2(ap,b0.y,acc[2][1]); acc[2][2]=ffma2(ap,b1.x,acc[2][2]); acc[2][3]=ffma2(ap,b1.y,acc[2][3]);
            ap=pack2(a0.w,a0.w); acc[3][0]=ffma2(ap,b0.x,acc[3][0]); acc[3][1]=ffma2(ap,b0.y,acc[3][1]); acc[3][2]=ffma2(ap,b1.x,acc[3][2]); acc[3][3]=ffma2(ap,b1.y,acc[3][3]);
            ap=pack2(a1.x,a1.x); acc[4][0]=ffma2(ap,b0.x,acc[4][0]); acc[4][1]=ffma2(ap,b0.y,acc[4][1]); acc[4][2]=ffma2(ap,b1.x,acc[4][2]); acc[4][3]=ffma2(ap,b1.y,acc[4][3]);
            ap=pack2(a1.y,a1.y); acc[5][0]=ffma2(ap,b0.x,acc[5][0]); acc[5][1]=ffma2(ap,b0.y,acc[5][1]); acc[5][2]=ffma2(ap,b1.x,acc[5][2]); acc[5][3]=ffma2(ap,b1.y,acc[5][3]);
            ap=pack2(a1.z,a1.z); acc[6][0]=ffma2(ap,b0.x,acc[6][0]); acc[6][1]=ffma2(ap,b0.y,acc[6][1]); acc[6][2]=ffma2(ap,b1.x,acc[6][2]); acc[6][3]=ffma2(ap,b1.y,acc[6][3]);
            ap=pack2(a1.w,a1.w); acc[7][0]=ffma2(ap,b0.x,acc[7][0]); acc[7][1]=ffma2(ap,b0.y,acc[7][1]); acc[7][2]=ffma2(ap,b1.x,acc[7][2]); acc[7][3]=ffma2(ap,b1.y,acc[7][3]);
        }
        if (t+1 < nt){
            int nb = cur ^ 1;
            #pragma unroll
            for (int j=0;j<4;j++){
                As[nb][j*4+0][tid]=ra[j].x; As[nb][j*4+1][tid]=ra[j].y;
                As[nb][j*4+2][tid]=ra[j].z; As[nb][j*4+3][tid]=ra[j].w;
            }
            *(float4*)&Bs[nb][brow][pb0] = rb0;
            *(float4*)&Bs[nb][brow][pb1] = rb1;
            __syncthreads();
            cur = nb;
        }
    }
    int colb = col0 + tx*8;
    float4 bia0, bia1;
    if (p.SPLIT == 1 && p.bias){
        bia0 = *(const float4*)(p.bias + colb);
        bia1 = *(const float4*)(p.bias + colb + 4);
    } else { bia0 = z4; bia1 = z4; }
    #pragma unroll
    for (int i=0;i<8;i++){
        int r = row0 + ty*8 + i;
        if (r >= p.M) continue;
        float2 v0 = unpack2(acc[i][0]), v1 = unpack2(acc[i][1]);
        float2 v2 = unpack2(acc[i][2]), v3 = unpack2(acc[i][3]);
        float4 o0 = make_float4(v0.x+bia0.x, v0.y+bia0.y, v1.x+bia0.z, v1.y+bia0.w);
        float4 o1 = make_float4(v2.x+bia1.x, v2.y+bia1.y, v3.x+bia1.z, v3.y+bia1.w);
        if (p.gelu){
            o0.x*=normcdff(o0.x); o0.y*=normcdff(o0.y); o0.z*=normcdff(o0.z); o0.w*=normcdff(o0.w);
            o1.x*=normcdff(o1.x); o1.y*=normcdff(o1.y); o1.z*=normcdff(o1.z); o1.w*=normcdff(o1.w);
        }
        *(float4*)(C + (long)r*p.ldc + colb)     = o0;
        *(float4*)(C + (long)r*p.ldc + colb + 4) = o1;
    }
}

// ---------------- fused flash attention, deferred normalization ----------------
__global__ __launch_bounds__(256,2) void flash_kernel(
    const float* __restrict__ qf, const float* __restrict__ kf,
    const float* __restrict__ vf, float* __restrict__ ao, float* __restrict__ fac)
{
    __shared__ float Qs[64][32];
    __shared__ float Ks[64][36];
    __shared__ float Vt[32][68];
    __shared__ float Ps[64][68];

    int zz = blockIdx.y; int b = zz >> 3, m = zz & 7;
    int q0 = blockIdx.x * 64;
    int tid = threadIdx.x, tx = tid & 15, ty = tid >> 4;
    const float scale = 0.17677669529663689f;
    const float4 z4 = make_float4(0.f,0.f,0.f,0.f);

    float mrow[4] = {-1e30f,-1e30f,-1e30f,-1e30f};
    float lrow[4] = {0.f,0.f,0.f,0.f};

    for (int cam=0; cam<6; cam++){
        u64 accA[4], accB[4];
        #pragma unroll
        for (int i=0;i<4;i++){ accA[i]=0ULL; accB[i]=0ULL; }
        const float* qbase = qf + ((long)(b*NCAM+cam)*HWQ)*DIM + m*DH;
        const float* kbase = kf + ((long)(b*NCAM+cam)*PK)*DIM + m*DH;
        const float* vbase = vf + ((long)(b*NCAM+cam)*PK)*DIM + m*DH;

        for (int kt=0; kt<10; kt++){
            int kk0 = kt*64;
            __syncthreads();
            if (kt == 0){
                #pragma unroll
                for (int t=0;t<2;t++){
                    int idx = tid + t*256;
                    int r = idx>>3, c4 = (idx&7)*4;
                    float4 v = z4;
                    if (q0+r < HWQ) v = *(const float4*)(qbase + (long)(q0+r)*DIM + c4);
                    v.x*=scale; v.y*=scale; v.z*=scale; v.w*=scale;
                    *(float4*)&Qs[r][c4] = v;
                }
            }
            #pragma unroll
            for (int t=0;t<2;t++){
                int idx = tid + t*256;
                int r = idx>>3, c4 = (idx&7)*4;
                float4 kv = z4, vv = z4;
                if (kk0 + r < PK){
                    kv = *(const float4*)(kbase + (long)(kk0+r)*DIM + c4);
                    vv = *(const float4*)(vbase + (long)(kk0+r)*DIM + c4);
                }
                *(float4*)&Ks[r][c4] = kv;
                Vt[c4+0][r]=vv.x; Vt[c4+1][r]=vv.y; Vt[c4+2][r]=vv.z; Vt[c4+3][r]=vv.w;
            }
            __syncthreads();

            u64 sacc[4][4];
            #pragma unroll
            for (int i=0;i<4;i++)
                #pragma unroll
                for (int j=0;j<4;j++) sacc[i][j]=0ULL;
            #pragma unroll
            for (int c4=0;c4<8;c4++){
                ulonglong2 qv[4], kv[4];
                #pragma unroll
                for (int i=0;i<4;i++) qv[i] = *(const ulonglong2*)&Qs[ty*4+i][c4*4];
                #pragma unroll
                for (int j=0;j<4;j++) kv[j] = *(const ulonglong2*)&Ks[tx+16*j][c4*4];
                #pragma unroll
                for (int i=0;i<4;i++)
                    #pragma unroll
                    for (int j=0;j<4;j++){
                        sacc[i][j]=ffma2(qv[i].x,kv[j].x,sacc[i][j]);
                        sacc[i][j]=ffma2(qv[i].y,kv[j].y,sacc[i][j]);
                    }
            }
            #pragma unroll
            for (int i=0;i<4;i++){
                float s_[4];
                float tmax = -1e30f;
                #pragma unroll
                for (int j=0;j<4;j++){
                    float2 t2 = unpack2(sacc[i][j]);
                    float s = t2.x + t2.y;
                    if (kk0 + tx + 16*j >= PK) s = -1e30f;
                    s_[j] = s; tmax = fmaxf(tmax, s);
                }
                #pragma unroll
                for (int off=1; off<16; off<<=1)
                    tmax = fmaxf(tmax, __shfl_xor_sync(0xffffffffu, tmax, off));
                float mnew = fmaxf(mrow[i], tmax);
                float corr = __expf(mrow[i] - mnew);
                float rsum = 0.f;
                #pragma unroll
                for (int j=0;j<4;j++){
                    float pv = __expf(s_[j] - mnew);
                    rsum += pv;
                    Ps[ty*4+i][tx+16*j] = pv;
                }
                #pragma unroll
                for (int off=1; off<16; off<<=1)
                    rsum += __shfl_xor_sync(0xffffffffu, rsum, off);
                lrow[i] = lrow[i]*corr + rsum;
                mrow[i] = mnew;
                u64 cp = pack2(corr, corr);
                accA[i] = fmul2(accA[i], cp);
                accB[i] = fmul2(accB[i], cp);
            }
            __syncthreads();

            #pragma unroll
            for (int k4=0;k4<16;k4++){
                ulonglong2 va = *(const ulonglong2*)&Vt[tx][k4*4];
                ulonglong2 vb = *(const ulonglong2*)&Vt[tx+16][k4*4];
                #pragma unroll
                for (int i=0;i<4;i++){
                    ulonglong2 pp = *(const ulonglong2*)&Ps[ty*4+i][k4*4];
                    accA[i]=ffma2(pp.x,va.x,accA[i]); accA[i]=ffma2(pp.y,va.y,accA[i]);
                    accB[i]=ffma2(pp.x,vb.x,accB[i]); accB[i]=ffma2(pp.y,vb.y,accB[i]);
                }
            }
        }
        // fold + stream this cam's UNNORMALIZED partial; snapshot running max
        #pragma unroll
        for (int i=0;i<4;i++){
            int qrow = q0 + ty*4 + i;
            if (qrow >= HWQ) continue;
            float2 a = unpack2(accA[i]);
            float2 v2 = unpack2(accB[i]);
            long rowoff = ((long)b*HWQ + qrow)*ND + cam*DIM + m*DH;
            ao[rowoff + tx]      = a.x + a.y;
            ao[rowoff + tx + 16] = v2.x + v2.y;
            if (tx == 0)
                fac[((long)(b*HWQ+qrow))*64 + cam*8 + m] = mrow[i];
        }
    }
    // final max + denominator
    #pragma unroll
    for (int i=0;i<4;i++){
        int qrow = q0 + ty*4 + i;
        if (qrow >= HWQ || tx != 0) continue;
        long f0 = ((long)(b*HWQ+qrow))*64;
        fac[f0 + 48 + m] = mrow[i];
        fac[f0 + 56 + m] = lrow[i];
    }
}

// ---------------- layernorm over 1536 with deferred softmax normalization ----
__global__ void ln1536_kernel(const float* __restrict__ x, const float* __restrict__ fac,
                              const float* __restrict__ g, const float* __restrict__ b,
                              float* __restrict__ y){
    __shared__ float sh[8];
    __shared__ float bmu, brs;
    __shared__ float f48[48];
    long row = blockIdx.x;
    const float* p = x + row * (long)ND;
    const float* fr = fac + row * 64;
    int tid = threadIdx.x;
    if (tid < 48){
        int mm = tid & 7;
        f48[tid] = __expf(fr[tid] - fr[48+mm]) / fr[56+mm];
    }
    __syncthreads();
    float vals[6]; float s = 0.f;
    #pragma unroll
    for (int i=0;i<6;i++){
        int c = tid + i*256;
        float fv = f48[((c>>8)<<3) + ((c>>5)&7)];
        vals[i] = p[c] * fv; s += vals[i];
    }
    s = warpRedSum(s);
    if ((tid & 31) == 0) sh[tid>>5] = s;
    __syncthreads();
    if (tid == 0){ float t=0.f; for (int i=0;i<8;i++) t += sh[i]; bmu = t / (float)ND; }
    __syncthreads();
    float mu = bmu, vs = 0.f;
    #pragma unroll
    for (int i=0;i<6;i++){ float d = vals[i]-mu; vs += d*d; }
    vs = warpRedSum(vs);
    if ((tid & 31) == 0) sh[tid>>5] = vs;
    __syncthreads();
    if (tid == 0){ float t=0.f; for (int i=0;i<8;i++) t += sh[i]; brs = rsqrtf(t/(float)ND + 1e-5f); }
    __syncthreads();
    float rs = brs;
    float* q = y + row * (long)ND;
    #pragma unroll
    for (int i=0;i<6;i++){ int c = tid + i*256; q[c] = (vals[i]-mu)*rs*g[c] + b[c]; }
}

// ---------------- proj reduce: xb = sum(part2)+bproj + sum(part1)+baddq ------
__global__ void reduce_proj_kernel(const float* __restrict__ p1, const float* __restrict__ p2,
                                   const float* __restrict__ baddq, const float* __restrict__ bproj,
                                   float* __restrict__ xb){
    long idx = (long)blockIdx.x * 256 + threadIdx.x;
    const long MN = (long)NB*HWQ*DIM;
    if (idx >= MN) return;
    int c = (int)(idx & 255);
    float v = bproj[c] + baddq[c];
    v += p1[idx] + p1[idx+MN] + p1[idx+2*MN];
    v += p2[idx] + p2[idx+MN] + p2[idx+2*MN];
    xb[idx] = v;
}

// ---------------- final: (sum ffn2 partials + b2) -> LN -> +x -> transpose ----
__global__ void final_kernel(const float* __restrict__ p3, const float* __restrict__ b2,
                             const float* __restrict__ x,
                             const float* __restrict__ g, const float* __restrict__ bb,
                             float* __restrict__ out){
    __shared__ float sh[8];
    __shared__ float bmu, brs;
    long row = blockIdx.x;
    const long MN = (long)NB*HWQ*DIM;
    int c = threadIdx.x;
    float v = p3[row*(long)DIM + c] + p3[MN + row*(long)DIM + c] + b2[c];
    float s = warpRedSum(v);
    if ((c & 31) == 0) sh[c>>5] = s;
    __syncthreads();
    if (c == 0){ float m=0.f; for (int i=0;i<8;i++) m += sh[i]; bmu = m / (float)DIM; }
    __syncthreads();
    float mu = bmu;
    float d = v - mu;
    float vs = warpRedSum(d*d);
    if ((c & 31) == 0) sh[c>>5] = vs;
    __syncthreads();
    if (c == 0){ float m=0.f; for (int i=0;i<8;i++) m += sh[i]; brs = rsqrtf(m/(float)DIM + 1e-5f); }
    __syncthreads();
    float y = d * brs * g[c] + bb[c] + x[row*(long)DIM + c];
    int b = (int)(row / HWQ), p = (int)(row % HWQ);
    out[((long)(b*DIM + c))*HWQ + p] = y;
}

// ---------------- host ----------------
static float* sym(const void* symbol){
    void* p = nullptr;
    cudaGetSymbolAddress(&p, symbol);
    return (float*)p;
}

static GemmP zeroP(){ GemmP p; memset(&p, 0, sizeof(p)); p.D1 = 1; p.SPLIT = 1; return p; }

static void launch_gemm(const GemmP& p, int batches){
    dim3 grid(p.N/64, (p.M+127)/128, batches * p.SPLIT);
    gemm_tc<<<grid, 128>>>(p);
}

extern "C" void kernel_launch(void* const* d_in, const int* in_sizes, int n_in,
                              void* d_out, int out_size){
    const float* q     = (const float*)d_in[0];
    const float* k     = (const float*)d_in[1];
    const float* v     = (const float*)d_in[2];
    const float* Wq    = (const float*)d_in[3];
    const float* bq    = (const float*)d_in[4];
    const float* Wk    = (const float*)d_in[5];
    const float* bk    = (const float*)d_in[6];
    const float* Wv    = (const float*)d_in[7];
    const float* bv    = (const float*)d_in[8];
    const float* Wproj = (const float*)d_in[9];
    const float* bproj = (const float*)d_in[10];
    const float* Waddq = (const float*)d_in[11];
    const float* baddq = (const float*)d_in[12];
    const float* W1    = (const float*)d_in[13];
    const float* b1    = (const float*)d_in[14];
    const float* W2    = (const float*)d_in[15];
    const float* b2    = (const float*)d_in[16];
    const float* g_pre = (const float*)d_in[17];
    const float* b_pre = (const float*)d_in[18];
    const float* g_nrm = (const float*)d_in[19];
    const float* b_nrm = (const float*)d_in[20];
    float* out = (float*)d_out;

    float* qT    = sym(g_qT);
    float* kpool = sym(g_kpool);
    float* vpool = sym(g_vpool);
    float* qf    = sym(g_qf);
    float* kf    = sym(g_kf);
    float* vf    = sym(g_vf);
    float* ao    = sym(g_attno);
    float* fac   = sym(g_fac);
    float* lnb   = sym(g_lnbuf);
    float* xb    = sym(g_xbuf);
    float* h1    = sym(g_h1);
    float* part1 = sym(g_part1);
    float* part2 = sym(g_part2);
    float* part3 = sym(g_part3);

    // 1) transpose q -> (b,p,nd)
    {
        dim3 grid((HWQ+31)/32, DIM/32, NB*NCAM);
        transpose_q_kernel<<<grid, dim3(32,8)>>>(q, qT);
    }
    // 2) pool k, v
    {
        long total = (long)NB*NCAM*DIM*PK;
        int blocks = (int)((total + 255) / 256);
        pool_kernel<<<blocks, 256>>>(k, kpool);
        pool_kernel<<<blocks, 256>>>(v, vpool);
    }
    // 3) add_q partials: qT @ Waddq, split-K x3
    {
        GemmP p = zeroP();
        p.A = qT; p.lda = ND; p.B = Waddq; p.ldb = DIM;
        p.C = part1; p.ldc = DIM; p.M = NB*HWQ; p.N = DIM;
        p.K = ND/3; p.SPLIT = 3; p.csplit = (long)NB*HWQ*DIM;
        launch_gemm(p, 1);
    }
    // 4) qf per (b,cam)
    {
        GemmP p = zeroP();
        p.A = qT; p.lda = ND; p.a0 = (long)HWQ*ND; p.a1 = DIM;
        p.B = Wq; p.ldb = DIM; p.bias = bq;
        p.C = qf; p.ldc = DIM; p.c0 = (long)NCAM*HWQ*DIM; p.c1 = (long)HWQ*DIM;
        p.M = HWQ; p.N = DIM; p.K = DIM; p.D1 = NCAM;
        launch_gemm(p, NB*NCAM);
    }
    // 5) kf, vf per (b,cam)
    {
        GemmP p = zeroP();
        p.A = kpool; p.lda = ND; p.a0 = (long)PK*ND; p.a1 = DIM;
        p.B = Wk; p.ldb = DIM; p.bias = bk;
        p.C = kf; p.ldc = DIM; p.c0 = (long)NCAM*PK*DIM; p.c1 = (long)PK*DIM;
        p.M = PK; p.N = DIM; p.K = DIM; p.D1 = NCAM;
        launch_gemm(p, NB*NCAM);
        p.A = vpool; p.B = Wv; p.bias = bv; p.C = vf;
        launch_gemm(p, NB*NCAM);
    }
    // 6) fused flash attention -> ao partials + fac
    {
        dim3 grid((HWQ+63)/64, NB*NHEAD);
        flash_kernel<<<grid, 256>>>(qf, kf, vf, ao, fac);
    }
    // 7) pre-layernorm (applies deferred softmax normalization)
    ln1536_kernel<<<NB*HWQ, 256>>>(ao, fac, g_pre, b_pre, lnb);
    // 8) proj partials: LN(out) @ Wproj, split-K x3
    {
        GemmP p = zeroP();
        p.A = lnb; p.lda = ND; p.B = Wproj; p.ldb = DIM;
        p.C = part2; p.ldc = DIM; p.M = NB*HWQ; p.N = DIM;
        p.K = ND/3; p.SPLIT = 3; p.csplit = (long)NB*HWQ*DIM;
        launch_gemm(p, 1);
    }
    // 8b) xb = sum(proj partials)+bproj + sum(addq partials)+baddq
    {
        long MN = (long)NB*HWQ*DIM;
        reduce_proj_kernel<<<(int)((MN+255)/256), 256>>>(part1, part2, baddq, bproj, xb);
    }
    // 9) h1 = gelu(x @ W1 + b1)
    {
        GemmP p = zeroP();
        p.A = xb; p.lda = DIM; p.B = W1; p.ldb = 2*DIM; p.bias = b1; p.gelu = 1;
        p.C = h1; p.ldc = 2*DIM; p.M = NB*HWQ; p.N = 2*DIM; p.K = DIM;
        launch_gemm(p, 1);
    }
    // 10) ffn2 partials: h1 @ W2, split-K x2
    {
        GemmP p = zeroP();
        p.A = h1; p.lda = 2*DIM; p.B = W2; p.ldb = DIM;
        p.C = part3; p.ldc = DIM; p.M = NB*HWQ; p.N = DIM;
        p.K = DIM; p.SPLIT = 2; p.csplit = (long)NB*HWQ*DIM;
        launch_gemm(p, 1);
    }
    // 11) out = transpose(x + LN(sum(part3)+b2))
    final_kernel<<<NB*HWQ, 256>>>(part3, b2, xb, g_nrm, b_nrm, out);
}